// round 9
// baseline (speedup 1.0000x reference)
#include <cuda_runtime.h>
#include <cuda_fp16.h>
#include <cstdint>

#define BB 256
#define NN 128
#define CC 256

// B = W^T fp16 image: [8 kchunks][256 rows][32 fp16] -> 128KB
__device__ __align__(16) unsigned char g_Bh[131072];

__device__ __forceinline__ uint32_t smem_u32(const void* p) {
    uint32_t a;
    asm("{ .reg .u64 t; cvta.to.shared.u64 t, %1; cvt.u32.u64 %0, t; }"
        : "=r"(a) : "l"(p));
    return a;
}

__device__ __forceinline__ void ldsm_x4(uint32_t& r0, uint32_t& r1, uint32_t& r2,
                                        uint32_t& r3, uint32_t addr) {
    asm volatile("ldmatrix.sync.aligned.m8n8.x4.shared.b16 {%0,%1,%2,%3}, [%4];"
                 : "=r"(r0), "=r"(r1), "=r"(r2), "=r"(r3) : "r"(addr));
}

__device__ __forceinline__ void mma16816(float* d, const uint32_t* a, const uint32_t* b) {
    asm volatile(
        "mma.sync.aligned.m16n8k16.row.col.f32.f16.f16.f32 "
        "{%0,%1,%2,%3}, {%4,%5,%6,%7}, {%8,%9}, {%0,%1,%2,%3};"
        : "+f"(d[0]), "+f"(d[1]), "+f"(d[2]), "+f"(d[3])
        : "r"(a[0]), "r"(a[1]), "r"(a[2]), "r"(a[3]), "r"(b[0]), "r"(b[1]));
}

__device__ __forceinline__ void cp16(uint32_t dst, const void* src) {
    asm volatile("cp.async.cg.shared.global [%0], [%1], 16;" :: "r"(dst), "l"(src));
}

__device__ __forceinline__ void pack_f16(const float* a, uint32_t* hv) {
    #pragma unroll
    for (int u = 0; u < 4; u++) {
        __half h0 = __float2half_rn(a[2 * u]);
        __half h1 = __float2half_rn(a[2 * u + 1]);
        hv[u] = ((uint32_t)__half_as_ushort(h1) << 16) | __half_as_ushort(h0);
    }
}

// ---------------------------------------------------------------------------
// Kernel 0: W^T fp16 image (coalesced).
// ---------------------------------------------------------------------------
__global__ void __launch_bounds__(256) prep_w_kernel(const float* __restrict__ W) {
    int e = blockIdx.x * 256 + threadIdx.x;   // 8192
    int lane = e & 31;
    int w = e >> 5;
    int n = (w & 7) * 32 + lane;
    int k0 = (w >> 3) * 8;
    float a[8];
    #pragma unroll
    for (int u = 0; u < 8; u++) a[u] = W[(size_t)(k0 + u) * CC + n];
    uint32_t hv[4];
    pack_f16(a, hv);
    size_t off = (size_t)(k0 >> 5) * 16384 + n * 64 + (k0 & 31) * 2;
    *(uint4*)(g_Bh + off) = make_uint4(hv[0], hv[1], hv[2], hv[3]);
}

// ---------------------------------------------------------------------------
// Fused kernel: conv (4-batched neighbor loads) -> SMEM A (fp16) -> 1-term
// fp16 HMMA GEMM + bias + LN + residual. 1 CTA/batch, 512 threads.
// ---------------------------------------------------------------------------
#define ROWPAD 80
#define SA      0               // 65536 : A image [8 chunks 8KB][128 rows 64B]
#define SB      65536           // 2 stages x 20480 (B fp16, rows padded 80B)
#define STAGE   20480
#define SNB     106496          // nb ushort[128][128] = 32768
#define SPAR    139264          // db, gamma, beta (3 x 1024)
#define SRED    142336          // redS 4096 + redQ 4096 (shK 9216 aliases SRED+SMI)
#define SMI     150528          // float2[128]
#define SMISC   151552          // shB 1024 | sge 512 | sgp 512 | scnt 512 | wmin 64 | mins 8
#define SMEMT   154624

__global__ void __launch_bounds__(512, 1) fused_kernel(
    const float* __restrict__ x, const float* __restrict__ eta,
    const float* __restrict__ phi, const float* __restrict__ ck,
    const float* __restrict__ cb, const float* __restrict__ db,
    const float* __restrict__ gamma, const float* __restrict__ beta,
    float* __restrict__ out)
{
    extern __shared__ char smem[];
    uint32_t sb = smem_u32(smem);
    int b = blockIdx.x;
    int t = threadIdx.x;
    int lane = t & 31;
    int w = t >> 5;

    const float* xb = x + (size_t)b * NN * CC;

    auto copy_stage = [&](int s, int kc) {
        uint32_t st = sb + SB + s * STAGE;
        #pragma unroll
        for (int p = 0; p < 2; p++) {
            int idx = t + p * 512;            // 1024 uint4 = 16KB
            int row = idx >> 2, seg = idx & 3;
            cp16(st + row * ROWPAD + seg * 16, g_Bh + (size_t)kc * 16384 + idx * 16);
        }
    };

    // ---- B chunk 0 prefetch (overlaps conv phase) ----
    copy_stage(0, 0);
    asm volatile("cp.async.commit_group;" ::: "memory");

    // params
    if (t < 256) {
        ((float*)(smem + SPAR))[t]        = db[t];
        ((float*)(smem + SPAR + 1024))[t] = gamma[t];
        ((float*)(smem + SPAR + 2048))[t] = beta[t];
    }

    // ---- conv-phase shared views ----
    float* shB   = (float*)(smem + SMISC);
    int*   sge   = (int*)(smem + SMISC + 1024);
    int*   sgp   = (int*)(smem + SMISC + 1536);
    int*   scnt  = (int*)(smem + SMISC + 2048);
    float* wmin  = (float*)(smem + SMISC + 2560);
    float* mins  = (float*)(smem + SMISC + 2624);
    float* shK   = (float*)(smem + SRED);          // 9216B spans SRED+SMI
    unsigned short (*nb)[NN] = (unsigned short (*)[NN])(smem + SNB);

    // ---- per-batch min ----
    float ve = (t < NN) ? eta[b * NN + t] : 1e30f;
    float vp = (t < NN) ? phi[b * NN + t] : 1e30f;
    #pragma unroll
    for (int o = 16; o > 0; o >>= 1) {
        ve = fminf(ve, __shfl_xor_sync(0xffffffffu, ve, o));
        vp = fminf(vp, __shfl_xor_sync(0xffffffffu, vp, o));
    }
    if (lane == 0 && w < 4) { wmin[w] = ve; wmin[4 + w] = vp; }
    __syncthreads();
    if (t == 0) {
        mins[0] = fminf(fminf(wmin[0], wmin[1]), fminf(wmin[2], wmin[3]));
        mins[1] = fminf(fminf(wmin[4], wmin[5]), fminf(wmin[6], wmin[7]));
    }
    __syncthreads();
    if (t < NN) {
        sge[t] = (int)((eta[b * NN + t] - mins[0]) / 0.05f);
        sgp[t] = (int)((phi[b * NN + t] - mins[1]) / 0.05f);
    }
    __syncthreads();

    // ---- neighbor lists (t<128), conv weights staged by the rest ----
    if (t < NN) {
        int gi = sge[t], pi = sgp[t];
        int cnt = 0;
        for (int j = 0; j < NN; j++) {
            unsigned dg = (unsigned)(sge[j] - gi + 1);
            unsigned dp = (unsigned)(sgp[j] - pi + 1);
            if (dg <= 2u && dp <= 2u)
                nb[t][cnt++] = (unsigned short)(j | ((dg * 3 + dp) << 8));
        }
        scnt[t] = cnt;
    } else {
        for (int i = t - 128; i < 9 * CC; i += 384) shK[i] = ck[i];
        if (t >= 256) shB[t - 256] = cb[t - 256];
    }
    __syncthreads();

    // ---- conv -> SMEM A (fp16, quad-group swizzle), 4-batched loads ----
    {
        int c0 = lane * 8;
        char* achunk = smem + SA + (lane >> 2) * 8192;    // chunk = c0>>5
        uint32_t q = (uint32_t)(lane & 3);                // quad within row

        #pragma unroll
        for (int s = 0; s < 8; s++) {
            int i = w * 8 + s;
            float acc[8];
            #pragma unroll
            for (int u = 0; u < 8; u++) acc[u] = shB[c0 + u];

            int cnt = scnt[i];
            for (int e = 0; e < cnt; e += 4) {
                int m = cnt - e;
                // 4 packed entries via two 4B LDS
                uint32_t pk01 = *(const uint32_t*)&nb[i][e];
                uint32_t pk23 = *(const uint32_t*)&nb[i][e + 2];
                int pk[4] = { (int)(pk01 & 0xFFFFu), (int)(pk01 >> 16),
                              (int)(pk23 & 0xFFFFu), (int)(pk23 >> 16) };
                float4 a0[4], a1[4], k0[4], k1[4];
                // issue all loads first (MLP up to 8 LDG.128 in flight)
                #pragma unroll
                for (int u = 0; u < 4; u++) {
                    if (u < m) {
                        int j = pk[u] & 0xFF;
                        int kk = pk[u] >> 8;
                        const float4* xp = (const float4*)(xb + (size_t)j * CC + c0);
                        a0[u] = xp[0];
                        a1[u] = xp[1];
                        const float4* kp = (const float4*)(shK + kk * CC + c0);
                        k0[u] = kp[0];
                        k1[u] = kp[1];
                    }
                }
                // consume
                #pragma unroll
                for (int u = 0; u < 4; u++) {
                    if (u < m) {
                        acc[0] += k0[u].x * a0[u].x; acc[1] += k0[u].y * a0[u].y;
                        acc[2] += k0[u].z * a0[u].z; acc[3] += k0[u].w * a0[u].w;
                        acc[4] += k1[u].x * a1[u].x; acc[5] += k1[u].y * a1[u].y;
                        acc[6] += k1[u].z * a1[u].z; acc[7] += k1[u].w * a1[u].w;
                    }
                }
            }

            uint32_t hv[4];
            pack_f16(acc, hv);
            uint32_t qs = q ^ ((uint32_t)(i >> 1) & 3u);
            *(uint4*)(achunk + i * 64 + qs * 16) = make_uint4(hv[0], hv[1], hv[2], hv[3]);
        }
    }
    __syncthreads();

    // ---- GEMM: M=128 N=256 K=256, 16 warps, warp tile 64x32, 1 term ----
    int mw = w & 1;
    int nw = w >> 1;

    float acc[4][4][4];
    #pragma unroll
    for (int i = 0; i < 4; i++)
        #pragma unroll
        for (int j = 0; j < 4; j++)
            #pragma unroll
            for (int d = 0; d < 4; d++) acc[i][j][d] = 0.f;

    int aRow0 = mw * 64 + (lane & 7) + ((lane >> 3) & 1) * 8;   // + mt*16
    uint32_t qk = (uint32_t)(lane >> 4);                         // 16B half of 32B

    int bRow = (lane & 7) + ((lane >= 16) ? 8 : 0);
    uint32_t bKb = (uint32_t)(((lane >> 3) & 1) * 16);
    uint32_t bOff = (uint32_t)((nw * 32 + bRow) * ROWPAD) + bKb;

    for (int kc = 0; kc < 8; kc++) {
        asm volatile("cp.async.wait_group 0;" ::: "memory");
        __syncthreads();
        if (kc < 7) {
            copy_stage((kc + 1) & 1, kc + 1);
            asm volatile("cp.async.commit_group;" ::: "memory");
        }

        uint32_t ca = sb + SA + kc * 8192;
        uint32_t sB = sb + SB + (kc & 1) * STAGE + bOff;

        #pragma unroll
        for (int ks = 0; ks < 2; ks++) {
            uint32_t av[4][4], bf[4][2];
            #pragma unroll
            for (int mt = 0; mt < 4; mt++) {
                int row = aRow0 + mt * 16;
                uint32_t qs = (((uint32_t)(ks * 2) + qk) ^ ((uint32_t)(row >> 1) & 3u)) * 16;
                ldsm_x4(av[mt][0], av[mt][1], av[mt][2], av[mt][3],
                        ca + row * 64 + qs);
            }
            #pragma unroll
            for (int np = 0; np < 2; np++) {
                uint32_t r0, r1, r2, r3;
                ldsm_x4(r0, r1, r2, r3, sB + np * (16 * ROWPAD) + ks * 32);
                bf[2 * np][0] = r0; bf[2 * np][1] = r1;
                bf[2 * np + 1][0] = r2; bf[2 * np + 1][1] = r3;
            }
            #pragma unroll
            for (int mt = 0; mt < 4; mt++)
                #pragma unroll
                for (int nt = 0; nt < 4; nt++)
                    mma16816(acc[mt][nt], av[mt], bf[nt]);
        }
    }

    // ---- epilogue: bias + LN + residual ----
    const float* s_db = (const float*)(smem + SPAR);
    const float* s_g  = (const float*)(smem + SPAR + 1024);
    const float* s_bt = (const float*)(smem + SPAR + 2048);
    float* redS = (float*)(smem + SRED);
    float* redQ = (float*)(smem + SRED + 4096);
    float2* smi = (float2*)(smem + SMI);

    int qr = lane >> 2, qc = lane & 3;
    int MW = mw * 64, NW = nw * 32;

    float S[4][2], Q[4][2];
    #pragma unroll
    for (int mt = 0; mt < 4; mt++) {
        S[mt][0] = S[mt][1] = 0.f;
        Q[mt][0] = Q[mt][1] = 0.f;
    }
    #pragma unroll
    for (int mt = 0; mt < 4; mt++)
        #pragma unroll
        for (int nt = 0; nt < 4; nt++)
            #pragma unroll
            for (int d = 0; d < 4; d++) {
                int col = NW + nt * 8 + qc * 2 + (d & 1);
                float v = acc[mt][nt][d] + s_db[col];
                acc[mt][nt][d] = v;
                S[mt][d >> 1] += v;
                Q[mt][d >> 1] += v * v;
            }
    #pragma unroll
    for (int mt = 0; mt < 4; mt++)
        #pragma unroll
        for (int h = 0; h < 2; h++) {
            #pragma unroll
            for (int off = 1; off <= 2; off <<= 1) {
                S[mt][h] += __shfl_xor_sync(0xffffffffu, S[mt][h], off);
                Q[mt][h] += __shfl_xor_sync(0xffffffffu, Q[mt][h], off);
            }
        }
    __syncthreads();
    if (qc == 0) {
        #pragma unroll
        for (int mt = 0; mt < 4; mt++)
            #pragma unroll
            for (int h = 0; h < 2; h++) {
                int row = MW + mt * 16 + qr + h * 8;
                redS[row * 8 + nw] = S[mt][h];
                redQ[row * 8 + nw] = Q[mt][h];
            }
    }
    __syncthreads();

    if (t < 128) {
        float s = 0.f, q = 0.f;
        #pragma unroll
        for (int k = 0; k < 8; k++) {
            s += redS[t * 8 + k];
            q += redQ[t * 8 + k];
        }
        float mean = s * (1.0f / 256.0f);
        float var = fmaf(-mean, mean, q * (1.0f / 256.0f));
        smi[t] = make_float2(mean, rsqrtf(var + 1e-6f));
    }
    __syncthreads();

    #pragma unroll
    for (int mt = 0; mt < 4; mt++)
        #pragma unroll
        for (int h = 0; h < 2; h++) {
            int row = MW + mt * 16 + qr + h * 8;
            float2 mv = smi[row];
            size_t rb = ((size_t)b * NN + row) * CC;
            #pragma unroll
            for (int nt = 0; nt < 4; nt++) {
                int col = NW + nt * 8 + qc * 2;
                float2 xv = *(const float2*)(x + rb + col);
                float v0 = (acc[mt][nt][h * 2]     - mv.x) * mv.y * s_g[col]     + s_bt[col]     + xv.x;
                float v1 = (acc[mt][nt][h * 2 + 1] - mv.x) * mv.y * s_g[col + 1] + s_bt[col + 1] + xv.y;
                *(float2*)(out + rb + col) = make_float2(v0, v1);
            }
        }
}

extern "C" void kernel_launch(void* const* d_in, const int* in_sizes, int n_in,
                              void* d_out, int out_size) {
    const float* x   = (const float*)d_in[0];
    const float* eta = (const float*)d_in[1];
    const float* phi = (const float*)d_in[2];
    const float* ck  = (const float*)d_in[3];
    const float* cb  = (const float*)d_in[4];
    const float* dw  = (const float*)d_in[5];
    const float* db  = (const float*)d_in[6];
    const float* gm  = (const float*)d_in[7];
    const float* bt  = (const float*)d_in[8];
    float* out = (float*)d_out;

    cudaFuncSetAttribute(fused_kernel,
                         cudaFuncAttributeMaxDynamicSharedMemorySize, SMEMT);

    prep_w_kernel<<<32, 256>>>(dw);
    fused_kernel<<<BB, 512, SMEMT>>>(x, eta, phi, ck, cb, db, gm, bt, out);
}

// round 10
// speedup vs baseline: 1.2117x; 1.2117x over previous
#include <cuda_runtime.h>
#include <cuda_fp16.h>
#include <cstdint>

#define BB 256
#define NN 128
#define CC 256

// B = W^T fp16 image: [8 kchunks][256 rows][32 fp16] -> 128KB
__device__ __align__(16) unsigned char g_Bh[131072];

__device__ __forceinline__ uint32_t smem_u32(const void* p) {
    uint32_t a;
    asm("{ .reg .u64 t; cvta.to.shared.u64 t, %1; cvt.u32.u64 %0, t; }"
        : "=r"(a) : "l"(p));
    return a;
}

__device__ __forceinline__ void ldsm_x4(uint32_t& r0, uint32_t& r1, uint32_t& r2,
                                        uint32_t& r3, uint32_t addr) {
    asm volatile("ldmatrix.sync.aligned.m8n8.x4.shared.b16 {%0,%1,%2,%3}, [%4];"
                 : "=r"(r0), "=r"(r1), "=r"(r2), "=r"(r3) : "r"(addr));
}

__device__ __forceinline__ void mma16816(float* d, const uint32_t* a, const uint32_t* b) {
    asm volatile(
        "mma.sync.aligned.m16n8k16.row.col.f32.f16.f16.f32 "
        "{%0,%1,%2,%3}, {%4,%5,%6,%7}, {%8,%9}, {%0,%1,%2,%3};"
        : "+f"(d[0]), "+f"(d[1]), "+f"(d[2]), "+f"(d[3])
        : "r"(a[0]), "r"(a[1]), "r"(a[2]), "r"(a[3]), "r"(b[0]), "r"(b[1]));
}

__device__ __forceinline__ void cp16(uint32_t dst, const void* src) {
    asm volatile("cp.async.cg.shared.global [%0], [%1], 16;" :: "r"(dst), "l"(src));
}

__device__ __forceinline__ void pack_f16(const float* a, uint32_t* hv) {
    #pragma unroll
    for (int u = 0; u < 4; u++) {
        __half h0 = __float2half_rn(a[2 * u]);
        __half h1 = __float2half_rn(a[2 * u + 1]);
        hv[u] = ((uint32_t)__half_as_ushort(h1) << 16) | __half_as_ushort(h0);
    }
}

// ---------------------------------------------------------------------------
// Kernel 0: W^T fp16 image (coalesced).
// ---------------------------------------------------------------------------
__global__ void __launch_bounds__(256) prep_w_kernel(const float* __restrict__ W) {
    int e = blockIdx.x * 256 + threadIdx.x;   // 8192
    int lane = e & 31;
    int w = e >> 5;
    int n = (w & 7) * 32 + lane;
    int k0 = (w >> 3) * 8;
    float a[8];
    #pragma unroll
    for (int u = 0; u < 8; u++) a[u] = W[(size_t)(k0 + u) * CC + n];
    uint32_t hv[4];
    pack_f16(a, hv);
    size_t off = (size_t)(k0 >> 5) * 16384 + n * 64 + (k0 & 31) * 2;
    *(uint4*)(g_Bh + off) = make_uint4(hv[0], hv[1], hv[2], hv[3]);
}

// ---------------------------------------------------------------------------
// Fused kernel: x staged to SMEM as fp16 (overlapped with nb build) -> conv
// from SMEM -> A (fp16 image) -> 1-term fp16 HMMA GEMM + bias + LN + residual.
// 1 CTA/batch, 512 threads.
// ---------------------------------------------------------------------------
#define ROWPAD 80
#define SA      0               // 65536 : A image [8 chunks 8KB][128 rows 64B]
#define SB      65536           // 2 stages x 20480 (B fp16, rows padded 80B)
#define STAGE   20480
#define SNB     106496          // nb ushort[128][128] = 32768
#define SXH     139264          // x fp16 [128 rows][256 ch] = 65536
#define SPAR    204800          // db, gamma, beta (3 x 1024)
#define SRED    207872          // redS 4096 + redQ 4096 (shK 9216 aliases SRED+SMI)
#define SMI     216064          // float2[128]
#define SMISC   217088          // shB 1024 | sge 512 | sgp 512 | scnt 512 | wmin 64 | mins 8
#define SMEMT   219776

__global__ void __launch_bounds__(512, 1) fused_kernel(
    const float* __restrict__ x, const float* __restrict__ eta,
    const float* __restrict__ phi, const float* __restrict__ ck,
    const float* __restrict__ cb, const float* __restrict__ db,
    const float* __restrict__ gamma, const float* __restrict__ beta,
    float* __restrict__ out)
{
    extern __shared__ char smem[];
    uint32_t sb = smem_u32(smem);
    int b = blockIdx.x;
    int t = threadIdx.x;
    int lane = t & 31;
    int w = t >> 5;

    const float* xb = x + (size_t)b * NN * CC;

    auto copy_stage = [&](int s, int kc) {
        uint32_t st = sb + SB + s * STAGE;
        #pragma unroll
        for (int p = 0; p < 2; p++) {
            int idx = t + p * 512;            // 1024 uint4 = 16KB
            int row = idx >> 2, seg = idx & 3;
            cp16(st + row * ROWPAD + seg * 16, g_Bh + (size_t)kc * 16384 + idx * 16);
        }
    };

    // ---- B chunk 0 prefetch (overlaps prologue) ----
    copy_stage(0, 0);
    asm volatile("cp.async.commit_group;" ::: "memory");

    // params
    if (t < 256) {
        ((float*)(smem + SPAR))[t]        = db[t];
        ((float*)(smem + SPAR + 1024))[t] = gamma[t];
        ((float*)(smem + SPAR + 2048))[t] = beta[t];
    }

    // ---- conv-phase shared views ----
    float* shB   = (float*)(smem + SMISC);
    int*   sge   = (int*)(smem + SMISC + 1024);
    int*   sgp   = (int*)(smem + SMISC + 1536);
    int*   scnt  = (int*)(smem + SMISC + 2048);
    float* wmin  = (float*)(smem + SMISC + 2560);
    float* mins  = (float*)(smem + SMISC + 2624);
    float* shK   = (float*)(smem + SRED);          // 9216B spans SRED+SMI
    unsigned short (*nb)[NN] = (unsigned short (*)[NN])(smem + SNB);

    // ---- per-batch min ----
    float ve = (t < NN) ? eta[b * NN + t] : 1e30f;
    float vp = (t < NN) ? phi[b * NN + t] : 1e30f;
    #pragma unroll
    for (int o = 16; o > 0; o >>= 1) {
        ve = fminf(ve, __shfl_xor_sync(0xffffffffu, ve, o));
        vp = fminf(vp, __shfl_xor_sync(0xffffffffu, vp, o));
    }
    if (lane == 0 && w < 4) { wmin[w] = ve; wmin[4 + w] = vp; }
    __syncthreads();
    if (t == 0) {
        mins[0] = fminf(fminf(wmin[0], wmin[1]), fminf(wmin[2], wmin[3]));
        mins[1] = fminf(fminf(wmin[4], wmin[5]), fminf(wmin[6], wmin[7]));
    }
    __syncthreads();
    if (t < NN) {
        sge[t] = (int)((eta[b * NN + t] - mins[0]) / 0.05f);
        sgp[t] = (int)((phi[b * NN + t] - mins[1]) / 0.05f);
    }
    __syncthreads();

    // ---- warps 0-3: neighbor lists; warps 4-15: stage conv weights + x fp16 ----
    if (t < NN) {
        int gi = sge[t], pi = sgp[t];
        int cnt = 0;
        for (int j = 0; j < NN; j++) {
            unsigned dg = (unsigned)(sge[j] - gi + 1);
            unsigned dp = (unsigned)(sgp[j] - pi + 1);
            if (dg <= 2u && dp <= 2u)
                nb[t][cnt++] = (unsigned short)(j | ((dg * 3 + dp) << 8));
        }
        scnt[t] = cnt;
    } else {
        int u = t - 128;                          // 0..383
        for (int i = u; i < 9 * CC; i += 384) shK[i] = ck[i];
        if (u < 256) shB[u] = cb[u];
        // x -> fp16 SMEM image (linear row-major, 512B per row)
        #pragma unroll
        for (int p = 0; p < 22; p++) {
            int idx = u + p * 384;                // 8192 float4 total
            if (idx < 8192) {
                float4 v = *(const float4*)(xb + (size_t)idx * 4);
                __half2 h0 = __floats2half2_rn(v.x, v.y);
                __half2 h1 = __floats2half2_rn(v.z, v.w);
                uint2 pkd;
                pkd.x = *(uint32_t*)&h0;
                pkd.y = *(uint32_t*)&h1;
                *(uint2*)(smem + SXH + idx * 8) = pkd;
            }
        }
    }
    __syncthreads();

    // ---- conv from SMEM xh -> SMEM A (fp16, quad-group swizzle) ----
    {
        int c0 = lane * 8;
        char* achunk = smem + SA + (lane >> 2) * 8192;    // chunk = c0>>5
        uint32_t q = (uint32_t)(lane & 3);                // quad within row
        uint32_t xOff = sb + SXH + (uint32_t)(c0 * 2);    // +j*512

        #pragma unroll
        for (int s = 0; s < 8; s++) {
            int i = w * 8 + s;
            float acc[8];
            #pragma unroll
            for (int u = 0; u < 8; u++) acc[u] = shB[c0 + u];

            int cnt = scnt[i];
            for (int e = 0; e < cnt; e++) {
                int pk = nb[i][e];
                int j = pk & 0xFF;
                int kk = pk >> 8;
                uint4 hx = *(const uint4*)(smem + (SXH + j * 512 + c0 * 2));
                float2 f0 = __half22float2(*(__half2*)&hx.x);
                float2 f1 = __half22float2(*(__half2*)&hx.y);
                float2 f2 = __half22float2(*(__half2*)&hx.z);
                float2 f3 = __half22float2(*(__half2*)&hx.w);
                const float4* kp = (const float4*)(shK + kk * CC + c0);
                float4 k0 = kp[0];
                float4 k1 = kp[1];
                acc[0] += k0.x * f0.x; acc[1] += k0.y * f0.y;
                acc[2] += k0.z * f1.x; acc[3] += k0.w * f1.y;
                acc[4] += k1.x * f2.x; acc[5] += k1.y * f2.y;
                acc[6] += k1.z * f3.x; acc[7] += k1.w * f3.y;
            }

            uint32_t hv[4];
            pack_f16(acc, hv);
            uint32_t qs = q ^ ((uint32_t)(i >> 1) & 3u);
            *(uint4*)(achunk + i * 64 + qs * 16) = make_uint4(hv[0], hv[1], hv[2], hv[3]);
        }
    }
    __syncthreads();

    // ---- GEMM: M=128 N=256 K=256, 16 warps, warp tile 64x32, 1 term ----
    int mw = w & 1;
    int nw = w >> 1;

    float acc[4][4][4];
    #pragma unroll
    for (int i = 0; i < 4; i++)
        #pragma unroll
        for (int j = 0; j < 4; j++)
            #pragma unroll
            for (int d = 0; d < 4; d++) acc[i][j][d] = 0.f;

    int aRow0 = mw * 64 + (lane & 7) + ((lane >> 3) & 1) * 8;   // + mt*16
    uint32_t qk = (uint32_t)(lane >> 4);                         // 16B half of 32B

    int bRow = (lane & 7) + ((lane >= 16) ? 8 : 0);
    uint32_t bKb = (uint32_t)(((lane >> 3) & 1) * 16);
    uint32_t bOff = (uint32_t)((nw * 32 + bRow) * ROWPAD) + bKb;

    for (int kc = 0; kc < 8; kc++) {
        asm volatile("cp.async.wait_group 0;" ::: "memory");
        __syncthreads();
        if (kc < 7) {
            copy_stage((kc + 1) & 1, kc + 1);
            asm volatile("cp.async.commit_group;" ::: "memory");
        }

        uint32_t ca = sb + SA + kc * 8192;
        uint32_t sB = sb + SB + (kc & 1) * STAGE + bOff;

        #pragma unroll
        for (int ks = 0; ks < 2; ks++) {
            uint32_t av[4][4], bf[4][2];
            #pragma unroll
            for (int mt = 0; mt < 4; mt++) {
                int row = aRow0 + mt * 16;
                uint32_t qs = (((uint32_t)(ks * 2) + qk) ^ ((uint32_t)(row >> 1) & 3u)) * 16;
                ldsm_x4(av[mt][0], av[mt][1], av[mt][2], av[mt][3],
                        ca + row * 64 + qs);
            }
            #pragma unroll
            for (int np = 0; np < 2; np++) {
                uint32_t r0, r1, r2, r3;
                ldsm_x4(r0, r1, r2, r3, sB + np * (16 * ROWPAD) + ks * 32);
                bf[2 * np][0] = r0; bf[2 * np][1] = r1;
                bf[2 * np + 1][0] = r2; bf[2 * np + 1][1] = r3;
            }
            #pragma unroll
            for (int mt = 0; mt < 4; mt++)
                #pragma unroll
                for (int nt = 0; nt < 4; nt++)
                    mma16816(acc[mt][nt], av[mt], bf[nt]);
        }
    }

    // ---- epilogue: bias + LN + residual ----
    const float* s_db = (const float*)(smem + SPAR);
    const float* s_g  = (const float*)(smem + SPAR + 1024);
    const float* s_bt = (const float*)(smem + SPAR + 2048);
    float* redS = (float*)(smem + SRED);
    float* redQ = (float*)(smem + SRED + 4096);
    float2* smi = (float2*)(smem + SMI);

    int qr = lane >> 2, qc = lane & 3;
    int MW = mw * 64, NW = nw * 32;

    float S[4][2], Q[4][2];
    #pragma unroll
    for (int mt = 0; mt < 4; mt++) {
        S[mt][0] = S[mt][1] = 0.f;
        Q[mt][0] = Q[mt][1] = 0.f;
    }
    #pragma unroll
    for (int mt = 0; mt < 4; mt++)
        #pragma unroll
        for (int nt = 0; nt < 4; nt++)
            #pragma unroll
            for (int d = 0; d < 4; d++) {
                int col = NW + nt * 8 + qc * 2 + (d & 1);
                float v = acc[mt][nt][d] + s_db[col];
                acc[mt][nt][d] = v;
                S[mt][d >> 1] += v;
                Q[mt][d >> 1] += v * v;
            }
    #pragma unroll
    for (int mt = 0; mt < 4; mt++)
        #pragma unroll
        for (int h = 0; h < 2; h++) {
            #pragma unroll
            for (int off = 1; off <= 2; off <<= 1) {
                S[mt][h] += __shfl_xor_sync(0xffffffffu, S[mt][h], off);
                Q[mt][h] += __shfl_xor_sync(0xffffffffu, Q[mt][h], off);
            }
        }
    __syncthreads();
    if (qc == 0) {
        #pragma unroll
        for (int mt = 0; mt < 4; mt++)
            #pragma unroll
            for (int h = 0; h < 2; h++) {
                int row = MW + mt * 16 + qr + h * 8;
                redS[row * 8 + nw] = S[mt][h];
                redQ[row * 8 + nw] = Q[mt][h];
            }
    }
    __syncthreads();

    if (t < 128) {
        float s = 0.f, q = 0.f;
        #pragma unroll
        for (int k = 0; k < 8; k++) {
            s += redS[t * 8 + k];
            q += redQ[t * 8 + k];
        }
        float mean = s * (1.0f / 256.0f);
        float var = fmaf(-mean, mean, q * (1.0f / 256.0f));
        smi[t] = make_float2(mean, rsqrtf(var + 1e-6f));
    }
    __syncthreads();

    #pragma unroll
    for (int mt = 0; mt < 4; mt++)
        #pragma unroll
        for (int h = 0; h < 2; h++) {
            int row = MW + mt * 16 + qr + h * 8;
            float2 mv = smi[row];
            size_t rb = ((size_t)b * NN + row) * CC;
            #pragma unroll
            for (int nt = 0; nt < 4; nt++) {
                int col = NW + nt * 8 + qc * 2;
                float2 xv = *(const float2*)(x + rb + col);
                float v0 = (acc[mt][nt][h * 2]     - mv.x) * mv.y * s_g[col]     + s_bt[col]     + xv.x;
                float v1 = (acc[mt][nt][h * 2 + 1] - mv.x) * mv.y * s_g[col + 1] + s_bt[col + 1] + xv.y;
                *(float2*)(out + rb + col) = make_float2(v0, v1);
            }
        }
}

extern "C" void kernel_launch(void* const* d_in, const int* in_sizes, int n_in,
                              void* d_out, int out_size) {
    const float* x   = (const float*)d_in[0];
    const float* eta = (const float*)d_in[1];
    const float* phi = (const float*)d_in[2];
    const float* ck  = (const float*)d_in[3];
    const float* cb  = (const float*)d_in[4];
    const float* dw  = (const float*)d_in[5];
    const float* db  = (const float*)d_in[6];
    const float* gm  = (const float*)d_in[7];
    const float* bt  = (const float*)d_in[8];
    float* out = (float*)d_out;

    cudaFuncSetAttribute(fused_kernel,
                         cudaFuncAttributeMaxDynamicSharedMemorySize, SMEMT);

    prep_w_kernel<<<32, 256>>>(dw);
    fused_kernel<<<BB, 512, SMEMT>>>(x, eta, phi, ck, cb, db, gm, bt, out);
}

// round 11
// speedup vs baseline: 1.2453x; 1.0277x over previous
#include <cuda_runtime.h>
#include <cuda_fp16.h>
#include <cstdint>

#define BB 256
#define NN 128
#define CC 256

// B = W^T fp16 image, pre-swizzled quad-XOR layout:
// [8 kchunks 16KB][256 rows 64B]; quad q at q ^ ((row>>1)&3). 128KB total.
__device__ __align__(16) unsigned char g_Bh[131072];

__device__ __forceinline__ uint32_t smem_u32(const void* p) {
    uint32_t a;
    asm("{ .reg .u64 t; cvta.to.shared.u64 t, %1; cvt.u32.u64 %0, t; }"
        : "=r"(a) : "l"(p));
    return a;
}

__device__ __forceinline__ void ldsm_x4(uint32_t& r0, uint32_t& r1, uint32_t& r2,
                                        uint32_t& r3, uint32_t addr) {
    asm volatile("ldmatrix.sync.aligned.m8n8.x4.shared.b16 {%0,%1,%2,%3}, [%4];"
                 : "=r"(r0), "=r"(r1), "=r"(r2), "=r"(r3) : "r"(addr));
}

__device__ __forceinline__ void mma16816(float* d, const uint32_t* a, const uint32_t* b) {
    asm volatile(
        "mma.sync.aligned.m16n8k16.row.col.f32.f16.f16.f32 "
        "{%0,%1,%2,%3}, {%4,%5,%6,%7}, {%8,%9}, {%0,%1,%2,%3};"
        : "+f"(d[0]), "+f"(d[1]), "+f"(d[2]), "+f"(d[3])
        : "r"(a[0]), "r"(a[1]), "r"(a[2]), "r"(a[3]), "r"(b[0]), "r"(b[1]));
}

__device__ __forceinline__ void cp16(uint32_t dst, const void* src) {
    asm volatile("cp.async.cg.shared.global [%0], [%1], 16;" :: "r"(dst), "l"(src));
}

__device__ __forceinline__ void pack_f16(const float* a, uint32_t* hv) {
    #pragma unroll
    for (int u = 0; u < 4; u++) {
        __half h0 = __float2half_rn(a[2 * u]);
        __half h1 = __float2half_rn(a[2 * u + 1]);
        hv[u] = ((uint32_t)__half_as_ushort(h1) << 16) | __half_as_ushort(h0);
    }
}

// ---------------------------------------------------------------------------
// Kernel 0: W^T fp16 image, pre-swizzled (coalesced reads).
// thread -> (n, k0): n = (w&7)*32+lane, k0 = (w>>3)*8 (one 16B quad).
// ---------------------------------------------------------------------------
__global__ void __launch_bounds__(256) prep_w_kernel(const float* __restrict__ W) {
    int e = blockIdx.x * 256 + threadIdx.x;   // 8192
    int lane = e & 31;
    int w = e >> 5;
    int n = (w & 7) * 32 + lane;
    int k0 = (w >> 3) * 8;
    float a[8];
    #pragma unroll
    for (int u = 0; u < 8; u++) a[u] = W[(size_t)(k0 + u) * CC + n];
    uint32_t hv[4];
    pack_f16(a, hv);
    uint32_t quad = (uint32_t)((k0 >> 3) & 3);
    uint32_t qs = quad ^ ((uint32_t)(n >> 1) & 3u);
    size_t off = (size_t)(k0 >> 5) * 16384 + (size_t)n * 64 + qs * 16;
    *(uint4*)(g_Bh + off) = make_uint4(hv[0], hv[1], hv[2], hv[3]);
}

// ---------------------------------------------------------------------------
// Fused kernel: full B (128KB) staged once via cp.async (overlapped with
// prologue), conv -> A image, then BARRIER-FREE 8-chunk GEMM, LN epilogue.
// 1 CTA/batch, 512 threads.
// ---------------------------------------------------------------------------
#define SA      0               // 65536 : A [8 chunks 8KB][128 rows 64B], quad-XOR
#define SB      65536           // 131072: full B image (same layout, 256 rows)
#define SNB     196608          // nb ushort[128][32] = 8192
#define SPAR    204800          // db, gamma, beta (3 x 1024)
#define SRED    207872          // redS 4096 + redQ 4096 (shK 9216 aliases SRED+SMI)
#define SMI     216064          // float2[128]
#define SMISC   217088          // shB 1024 | sge 512 | sgp 512 | scnt 512 | wmin 64 | mins 8
#define SMEMT   219776

__global__ void __launch_bounds__(512, 1) fused_kernel(
    const float* __restrict__ x, const float* __restrict__ eta,
    const float* __restrict__ phi, const float* __restrict__ ck,
    const float* __restrict__ cb, const float* __restrict__ db,
    const float* __restrict__ gamma, const float* __restrict__ beta,
    float* __restrict__ out)
{
    extern __shared__ char smem[];
    uint32_t sb = smem_u32(smem);
    int b = blockIdx.x;
    int t = threadIdx.x;
    int lane = t & 31;
    int w = t >> 5;

    const float* xb = x + (size_t)b * NN * CC;

    // ---- stage ENTIRE B (128KB) once; overlaps the whole prologue ----
    #pragma unroll
    for (int p = 0; p < 16; p++) {
        int idx = t + p * 512;                // 8192 uint4
        cp16(sb + SB + idx * 16, g_Bh + (size_t)idx * 16);
    }
    asm volatile("cp.async.commit_group;" ::: "memory");

    // params
    if (t < 256) {
        ((float*)(smem + SPAR))[t]        = db[t];
        ((float*)(smem + SPAR + 1024))[t] = gamma[t];
        ((float*)(smem + SPAR + 2048))[t] = beta[t];
    }

    // ---- conv-phase shared views ----
    float* shB   = (float*)(smem + SMISC);
    int*   sge   = (int*)(smem + SMISC + 1024);
    int*   sgp   = (int*)(smem + SMISC + 1536);
    int*   scnt  = (int*)(smem + SMISC + 2048);
    float* wmin  = (float*)(smem + SMISC + 2560);
    float* mins  = (float*)(smem + SMISC + 2624);
    float* shK   = (float*)(smem + SRED);          // 9216B spans SRED+SMI
    unsigned short (*nb)[32] = (unsigned short (*)[32])(smem + SNB);

    // ---- per-batch min ----
    float ve = (t < NN) ? eta[b * NN + t] : 1e30f;
    float vp = (t < NN) ? phi[b * NN + t] : 1e30f;
    #pragma unroll
    for (int o = 16; o > 0; o >>= 1) {
        ve = fminf(ve, __shfl_xor_sync(0xffffffffu, ve, o));
        vp = fminf(vp, __shfl_xor_sync(0xffffffffu, vp, o));
    }
    if (lane == 0 && w < 4) { wmin[w] = ve; wmin[4 + w] = vp; }
    __syncthreads();
    if (t == 0) {
        mins[0] = fminf(fminf(wmin[0], wmin[1]), fminf(wmin[2], wmin[3]));
        mins[1] = fminf(fminf(wmin[4], wmin[5]), fminf(wmin[6], wmin[7]));
    }
    __syncthreads();
    if (t < NN) {
        sge[t] = (int)((eta[b * NN + t] - mins[0]) / 0.05f);
        sgp[t] = (int)((phi[b * NN + t] - mins[1]) / 0.05f);
    }
    __syncthreads();

    // ---- neighbor lists (t<128, cap 32), conv weights staged by the rest ----
    if (t < NN) {
        int gi = sge[t], pi = sgp[t];
        int cnt = 0;
        for (int j = 0; j < NN; j++) {
            unsigned dg = (unsigned)(sge[j] - gi + 1);
            unsigned dp = (unsigned)(sgp[j] - pi + 1);
            if (dg <= 2u && dp <= 2u && cnt < 32)
                nb[t][cnt++] = (unsigned short)(j | ((dg * 3 + dp) << 8));
        }
        scnt[t] = cnt;
    } else {
        int u = t - 128;
        for (int i = u; i < 9 * CC; i += 384) shK[i] = ck[i];
        if (u < 256) shB[u] = cb[u];
    }
    __syncthreads();

    // ---- conv -> SMEM A (fp16, quad-group swizzle) ----
    {
        int c0 = lane * 8;
        char* achunk = smem + SA + (lane >> 2) * 8192;    // chunk = c0>>5
        uint32_t q = (uint32_t)(lane & 3);                // quad within row

        #pragma unroll
        for (int s = 0; s < 8; s++) {
            int i = w * 8 + s;
            float acc[8];
            #pragma unroll
            for (int u = 0; u < 8; u++) acc[u] = shB[c0 + u];

            int cnt = scnt[i];
            for (int e = 0; e < cnt; e++) {
                int pk = nb[i][e];
                int j = pk & 0xFF;
                int kk = pk >> 8;
                const float4* xp = (const float4*)(xb + (size_t)j * CC + c0);
                float4 a0 = xp[0];
                float4 a1 = xp[1];
                const float4* kp = (const float4*)(shK + kk * CC + c0);
                float4 k0 = kp[0];
                float4 k1 = kp[1];
                acc[0] += k0.x * a0.x; acc[1] += k0.y * a0.y;
                acc[2] += k0.z * a0.z; acc[3] += k0.w * a0.w;
                acc[4] += k1.x * a1.x; acc[5] += k1.y * a1.y;
                acc[6] += k1.z * a1.z; acc[7] += k1.w * a1.w;
            }

            uint32_t hv[4];
            pack_f16(acc, hv);
            uint32_t qs = q ^ ((uint32_t)(i >> 1) & 3u);
            *(uint4*)(achunk + i * 64 + qs * 16) = make_uint4(hv[0], hv[1], hv[2], hv[3]);
        }
    }
    // B copy + A image both must be complete; single rendezvous
    asm volatile("cp.async.wait_group 0;" ::: "memory");
    __syncthreads();

    // ---- GEMM: M=128 N=256 K=256, 16 warps, warp tile 64x32 — NO barriers ----
    int mw = w & 1;
    int nw = w >> 1;

    float acc[4][4][4];
    #pragma unroll
    for (int i = 0; i < 4; i++)
        #pragma unroll
        for (int j = 0; j < 4; j++)
            #pragma unroll
            for (int d = 0; d < 4; d++) acc[i][j][d] = 0.f;

    int aRow0 = mw * 64 + (lane & 7) + ((lane >> 3) & 1) * 8;   // + mt*16
    uint32_t qk = (uint32_t)(lane >> 4);                         // A: 16B half of 32B

    // B lane mapping: rows nw*32 + bRow (+ np*16), quad = ks*2 + qb
    int bRow = (lane & 7) + ((lane >= 16) ? 8 : 0);
    uint32_t qb = (uint32_t)((lane >> 3) & 1);
    int bR[2];
    uint32_t bSw[2];
    #pragma unroll
    for (int np = 0; np < 2; np++) {
        bR[np] = nw * 32 + bRow + np * 16;
        bSw[np] = ((uint32_t)(bR[np] >> 1) & 3u);
    }

    for (int kc = 0; kc < 8; kc++) {
        uint32_t ca = sb + SA + kc * 8192;
        uint32_t cbase = sb + SB + kc * 16384;

        #pragma unroll
        for (int ks = 0; ks < 2; ks++) {
            uint32_t av[4][4], bf[4][2];
            #pragma unroll
            for (int mt = 0; mt < 4; mt++) {
                int row = aRow0 + mt * 16;
                uint32_t qs = (((uint32_t)(ks * 2) + qk) ^ ((uint32_t)(row >> 1) & 3u)) * 16;
                ldsm_x4(av[mt][0], av[mt][1], av[mt][2], av[mt][3],
                        ca + row * 64 + qs);
            }
            #pragma unroll
            for (int np = 0; np < 2; np++) {
                uint32_t qs = (((uint32_t)(ks * 2) + qb) ^ bSw[np]) * 16;
                uint32_t r0, r1, r2, r3;
                ldsm_x4(r0, r1, r2, r3, cbase + bR[np] * 64 + qs);
                bf[2 * np][0] = r0; bf[2 * np][1] = r1;
                bf[2 * np + 1][0] = r2; bf[2 * np + 1][1] = r3;
            }
            #pragma unroll
            for (int mt = 0; mt < 4; mt++)
                #pragma unroll
                for (int nt = 0; nt < 4; nt++)
                    mma16816(acc[mt][nt], av[mt], bf[nt]);
        }
    }

    // ---- epilogue: bias + LN + residual ----
    const float* s_db = (const float*)(smem + SPAR);
    const float* s_g  = (const float*)(smem + SPAR + 1024);
    const float* s_bt = (const float*)(smem + SPAR + 2048);
    float* redS = (float*)(smem + SRED);
    float* redQ = (float*)(smem + SRED + 4096);
    float2* smi = (float2*)(smem + SMI);

    int qr = lane >> 2, qc = lane & 3;
    int MW = mw * 64, NW = nw * 32;

    float S[4][2], Q[4][2];
    #pragma unroll
    for (int mt = 0; mt < 4; mt++) {
        S[mt][0] = S[mt][1] = 0.f;
        Q[mt][0] = Q[mt][1] = 0.f;
    }
    #pragma unroll
    for (int mt = 0; mt < 4; mt++)
        #pragma unroll
        for (int nt = 0; nt < 4; nt++)
            #pragma unroll
            for (int d = 0; d < 4; d++) {
                int col = NW + nt * 8 + qc * 2 + (d & 1);
                float v = acc[mt][nt][d] + s_db[col];
                acc[mt][nt][d] = v;
                S[mt][d >> 1] += v;
                Q[mt][d >> 1] += v * v;
            }
    #pragma unroll
    for (int mt = 0; mt < 4; mt++)
        #pragma unroll
        for (int h = 0; h < 2; h++) {
            #pragma unroll
            for (int off = 1; off <= 2; off <<= 1) {
                S[mt][h] += __shfl_xor_sync(0xffffffffu, S[mt][h], off);
                Q[mt][h] += __shfl_xor_sync(0xffffffffu, Q[mt][h], off);
            }
        }
    __syncthreads();    // shK (aliasing SRED/SMI) fully dead; GEMM reads done
    if (qc == 0) {
        #pragma unroll
        for (int mt = 0; mt < 4; mt++)
            #pragma unroll
            for (int h = 0; h < 2; h++) {
                int row = MW + mt * 16 + qr + h * 8;
                redS[row * 8 + nw] = S[mt][h];
                redQ[row * 8 + nw] = Q[mt][h];
            }
    }
    __syncthreads();

    if (t < 128) {
        float s = 0.f, q = 0.f;
        #pragma unroll
        for (int k = 0; k < 8; k++) {
            s += redS[t * 8 + k];
            q += redQ[t * 8 + k];
        }
        float mean = s * (1.0f / 256.0f);
        float var = fmaf(-mean, mean, q * (1.0f / 256.0f));
        smi[t] = make_float2(mean, rsqrtf(var + 1e-6f));
    }
    __syncthreads();

    #pragma unroll
    for (int mt = 0; mt < 4; mt++)
        #pragma unroll
        for (int h = 0; h < 2; h++) {
            int row = MW + mt * 16 + qr + h * 8;
            float2 mv = smi[row];
            size_t rb = ((size_t)b * NN + row) * CC;
            #pragma unroll
            for (int nt = 0; nt < 4; nt++) {
                int col = NW + nt * 8 + qc * 2;
                float2 xv = *(const float2*)(x + rb + col);
                float v0 = (acc[mt][nt][h * 2]     - mv.x) * mv.y * s_g[col]     + s_bt[col]     + xv.x;
                float v1 = (acc[mt][nt][h * 2 + 1] - mv.x) * mv.y * s_g[col + 1] + s_bt[col + 1] + xv.y;
                *(float2*)(out + rb + col) = make_float2(v0, v1);
            }
        }
}

extern "C" void kernel_launch(void* const* d_in, const int* in_sizes, int n_in,
                              void* d_out, int out_size) {
    const float* x   = (const float*)d_in[0];
    const float* eta = (const float*)d_in[1];
    const float* phi = (const float*)d_in[2];
    const float* ck  = (const float*)d_in[3];
    const float* cb  = (const float*)d_in[4];
    const float* dw  = (const float*)d_in[5];
    const float* db  = (const float*)d_in[6];
    const float* gm  = (const float*)d_in[7];
    const float* bt  = (const float*)d_in[8];
    float* out = (float*)d_out;

    cudaFuncSetAttribute(fused_kernel,
                         cudaFuncAttributeMaxDynamicSharedMemorySize, SMEMT);

    prep_w_kernel<<<32, 256>>>(dw);
    fused_kernel<<<BB, 512, SMEMT>>>(x, eta, phi, ck, cb, db, gm, bt, out);
}